// round 16
// baseline (speedup 1.0000x reference)
#include <cuda_runtime.h>
#include <cuda_fp16.h>
#include <cstdint>
#include <cstring>
#include <cfloat>

// VectorQuantizer: B=131072, D=64, K=1024, fp32.
// R16 = R14 (persistent fp16 mma.sync, codebook in smem, direct A-fragment
// build from fp32 staging) with TOP-8 pair keys: finalize duels the complete
// within-margin candidate prefix (<=7 pairs, 2 threads/row), so the exact
// fallback kernel is nearly empty.

#define VQ_B 131072
#define VQ_K 1024
#define VQ_D 64
#define ROWS 128
#define THREADS 256
#define NTILES (VQ_B / ROWS)   // 1024
#define GRID_MAIN 148
#define STG_PITCH 272
#define STG_BYTES (ROWS * STG_PITCH)  // 34816

__device__ float g_esq[VQ_K];
__device__ int g_emax2_bits = 0;
__device__ int g_flag_count;
__device__ int g_flag_rows[VQ_B];
__device__ __half g_eh[(size_t)VQ_K * VQ_D];   // fp16 e, granule-swizzled

// Dynamic smem layout (bytes)
#define ES_OFF     0         // 131072
#define STAGE_OFF  131072    // 2 * 34816 = 69632
#define ESQ_OFF    200704    // 4096
#define KEYS_OFF   204800    // [2][128][8] uint32 = 8192
#define XSQ_OFF    212992    // 512
#define DBS_OFF    213504    // 256 floats = 1024
#define DBI_OFF    214528    // 256 ints = 1024
#define SMEM_TOTAL 215552

// ---------------- PTX helpers ----------------
static __device__ __forceinline__ uint32_t smem_u32(const void* p) {
    uint32_t a;
    asm("{ .reg .u64 t; cvta.to.shared.u64 t, %1; cvt.u32.u64 %0, t; }" : "=r"(a) : "l"(p));
    return a;
}
#define CP_ASYNC16(dst, src) \
    asm volatile("cp.async.cg.shared.global [%0], [%1], 16;" :: "r"(dst), "l"(src) : "memory")
#define CP_COMMIT() asm volatile("cp.async.commit_group;" ::: "memory")
#define CP_WAIT1() asm volatile("cp.async.wait_group 1;" ::: "memory")
#define LDSM_X4(r0, r1, r2, r3, a) \
    asm volatile("ldmatrix.sync.aligned.m8n8.x4.shared.b16 {%0,%1,%2,%3}, [%4];" \
                 : "=r"(r0), "=r"(r1), "=r"(r2), "=r"(r3) : "r"(a))
#define MMA16816(c0, c1, c2, c3, a0, a1, a2, a3, b0, b1) \
    asm volatile("mma.sync.aligned.m16n8k16.row.col.f32.f16.f16.f32 " \
                 "{%0,%1,%2,%3}, {%4,%5,%6,%7}, {%8,%9}, {%0,%1,%2,%3};" \
                 : "+f"(c0), "+f"(c1), "+f"(c2), "+f"(c3) \
                 : "r"(a0), "r"(a1), "r"(a2), "r"(a3), "r"(b0), "r"(b1))

// sorted top-8 insert (bubbling; k[0] <= ... <= k[7])
static __device__ __forceinline__ void ins8(uint32_t k[8], uint32_t u) {
#pragma unroll
    for (int i = 0; i < 8; i++) {
        uint32_t mx = max(k[i], u);
        k[i] = min(k[i], u);
        u = mx;
    }
}

// f32x2 packed math (fallback kernel)
#define FMA_F32X2(acc, a, b) asm("fma.rn.f32x2 %0, %1, %2, %0;" : "+l"(acc) : "l"(a), "l"(b))
#define ADD_F32X2(d, a, b) asm("add.rn.f32x2 %0, %1, %2;" : "=l"(d) : "l"(a), "l"(b))
static __device__ __forceinline__ float2 u64f2(uint64_t u) { float2 v; memcpy(&v, &u, 8); return v; }
static __device__ __forceinline__ uint64_t f2u64(float2 v) { uint64_t u; memcpy(&u, &v, 8); return u; }

static __device__ __forceinline__ uint32_t h2pack(float a, float b) {
    __half2 h = __floats2half2_rn(a, b);
    uint32_t u;
    memcpy(&u, &h, 4);
    return u;
}

// ---------------- prologue: e -> fp16 (granule-swizzled) + esq + emax ----------------
__global__ void vq_prep_e(const float* __restrict__ e) {
    int t = blockIdx.x * blockDim.x + threadIdx.x;
    if (t == 0) g_flag_count = 0;
    if (t >= VQ_K * 8) return;
    int c = t >> 3, g = t & 7;
    const float4* p = reinterpret_cast<const float4*>(e + (size_t)c * VQ_D + g * 8);
    float4 v0 = p[0], v1 = p[1];
    float s = v0.x * v0.x + v0.y * v0.y + v0.z * v0.z + v0.w * v0.w +
              v1.x * v1.x + v1.y * v1.y + v1.z * v1.z + v1.w * v1.w;
    __half2 h[4] = {__floats2half2_rn(v0.x, v0.y), __floats2half2_rn(v0.z, v0.w),
                    __floats2half2_rn(v1.x, v1.y), __floats2half2_rn(v1.z, v1.w)};
    uint4 pk;
    memcpy(&pk, h, 16);
    int gp = g ^ (c & 7);
    *reinterpret_cast<uint4*>(&g_eh[(size_t)c * VQ_D + gp * 8]) = pk;
    s += __shfl_down_sync(~0u, s, 4, 8);
    s += __shfl_down_sync(~0u, s, 2, 8);
    s += __shfl_down_sync(~0u, s, 1, 8);
    if (g == 0) {
        g_esq[c] = s;
        atomicMax(&g_emax2_bits, __float_as_int(s));
    }
}

// exact fp32 score with 4 split accumulators
static __device__ __forceinline__ float exact_score(const float4* xr, const float* e, int code,
                                                    float esq) {
    const float4* er = reinterpret_cast<const float4*>(e + (size_t)code * VQ_D);
    float a0 = 0.f, a1 = 0.f, a2 = 0.f, a3 = 0.f;
#pragma unroll
    for (int i = 0; i < 16; i += 4) {
        float4 xa = xr[i], ba = er[i];
        float4 xb = xr[i + 1], bb = er[i + 1];
        float4 xc = xr[i + 2], bc = er[i + 2];
        float4 xd = xr[i + 3], bd = er[i + 3];
        a0 = fmaf(xa.x, ba.x, a0); a0 = fmaf(xa.y, ba.y, a0);
        a0 = fmaf(xa.z, ba.z, a0); a0 = fmaf(xa.w, ba.w, a0);
        a1 = fmaf(xb.x, bb.x, a1); a1 = fmaf(xb.y, bb.y, a1);
        a1 = fmaf(xb.z, bb.z, a1); a1 = fmaf(xb.w, bb.w, a1);
        a2 = fmaf(xc.x, bc.x, a2); a2 = fmaf(xc.y, bc.y, a2);
        a2 = fmaf(xc.z, bc.z, a2); a2 = fmaf(xc.w, bc.w, a2);
        a3 = fmaf(xd.x, bd.x, a3); a3 = fmaf(xd.y, bd.y, a3);
        a3 = fmaf(xd.z, bd.z, a3); a3 = fmaf(xd.w, bd.w, a3);
    }
    return fmaf(-2.f, (a0 + a1) + (a2 + a3), esq);
}

// ---------------- main ----------------
__global__ void __launch_bounds__(THREADS, 1) vq_main(const float* __restrict__ x,
                                                      const float* __restrict__ e,
                                                      float* __restrict__ out) {
    extern __shared__ __align__(16) unsigned char dsm[];
    const uint32_t sb = smem_u32(dsm);
    float* s_esq = reinterpret_cast<float*>(dsm + ESQ_OFF);
    uint32_t* s_keys = reinterpret_cast<uint32_t*>(dsm + KEYS_OFF);  // [2][128][8]
    float* s_xsq = reinterpret_cast<float*>(dsm + XSQ_OFF);
    float* s_dbs = reinterpret_cast<float*>(dsm + DBS_OFF);
    int* s_dbi = reinterpret_cast<int*>(dsm + DBI_OFF);
    __shared__ int s_widx[ROWS];

    const int tid = threadIdx.x;
    const int warp = tid >> 5, lane = tid & 31;
    const int rg = warp & 3;
    const int wh = warp >> 2;

    auto stage_tile = [&](int tile, int b) {
#pragma unroll
        for (int i = 0; i < 8; i++) {
            int idx = tid + i * THREADS;
            int r = idx >> 4, q = idx & 15;
            CP_ASYNC16(sb + STAGE_OFF + b * STG_BYTES + r * STG_PITCH + q * 16,
                       reinterpret_cast<const char*>(x) +
                           ((size_t)tile * ROWS + r) * (VQ_D * 4) + q * 16);
        }
    };

#pragma unroll
    for (int i = 0; i < 32; i++) {
        int line = tid + i * THREADS;
        CP_ASYNC16(sb + ES_OFF + line * 16, reinterpret_cast<const char*>(g_eh) + line * 16);
    }
    CP_ASYNC16(sb + ESQ_OFF + tid * 16, reinterpret_cast<const char*>(g_esq) + tid * 16);
    stage_tile(blockIdx.x, 0);
    CP_COMMIT();
    if (blockIdx.x + GRID_MAIN < NTILES) stage_tile(blockIdx.x + GRID_MAIN, 1);
    CP_COMMIT();

    const float emax = sqrtf(__int_as_float(g_emax2_bits));
    const int lc = lane & 7, lm = lane >> 3;
    const uint32_t bA0 = sb + ES_OFF + (wh * 4) * 16384 + (lc * 64 + ((lm ^ lc) * 8)) * 2;
    const uint32_t bB0 = sb + ES_OFF + (wh * 4) * 16384 + (lc * 64 + (((lm + 4) ^ lc) * 8)) * 2;
    const int gcl = 2 * (lane & 3);

    int buf = 0;
    for (int tile = blockIdx.x; tile < NTILES; tile += GRID_MAIN, buf ^= 1) {
        const int row0 = tile * ROWS;

        CP_WAIT1();
        __syncthreads();

        // A fragments directly from fp32 staging (canonical m16n8k16 layout)
        uint32_t A0[4][4], A1[4][4];
        {
            const unsigned char* stg = dsm + STAGE_OFF + buf * STG_BYTES;
            const int qr = lane >> 2;
            const int kc = (lane & 3) * 2;
            const int ra = rg * 32 + qr;
#pragma unroll
            for (int ks = 0; ks < 4; ks++) {
                const int k0 = 16 * ks + kc;
#pragma unroll
                for (int half = 0; half < 2; half++) {
                    uint32_t (*A)[4] = half ? A1 : A0;
                    const int r_lo = ra + half * 16;
                    const int r_hi = r_lo + 8;
                    float2 v0 = *reinterpret_cast<const float2*>(stg + r_lo * STG_PITCH + k0 * 4);
                    float2 v1 = *reinterpret_cast<const float2*>(stg + r_hi * STG_PITCH + k0 * 4);
                    float2 v2 = *reinterpret_cast<const float2*>(stg + r_lo * STG_PITCH + (k0 + 8) * 4);
                    float2 v3 = *reinterpret_cast<const float2*>(stg + r_hi * STG_PITCH + (k0 + 8) * 4);
                    A[ks][0] = h2pack(v0.x, v0.y);
                    A[ks][1] = h2pack(v1.x, v1.y);
                    A[ks][2] = h2pack(v2.x, v2.y);
                    A[ks][3] = h2pack(v3.x, v3.y);
                }
            }
        }
        __syncthreads();

        if (tile + 2 * GRID_MAIN < NTILES) stage_tile(tile + 2 * GRID_MAIN, buf);
        CP_COMMIT();

        // per-row squared norms from A fragments
        float xq0, xq1, xq2, xq3;
        {
            float t0 = 0.f, t1 = 0.f, t2 = 0.f, t3 = 0.f;
#pragma unroll
            for (int ks = 0; ks < 4; ks++) {
                float2 f;
                f = __half22float2(*reinterpret_cast<__half2*>(&A0[ks][0]));
                t0 = fmaf(f.x, f.x, t0); t0 = fmaf(f.y, f.y, t0);
                f = __half22float2(*reinterpret_cast<__half2*>(&A0[ks][2]));
                t0 = fmaf(f.x, f.x, t0); t0 = fmaf(f.y, f.y, t0);
                f = __half22float2(*reinterpret_cast<__half2*>(&A0[ks][1]));
                t1 = fmaf(f.x, f.x, t1); t1 = fmaf(f.y, f.y, t1);
                f = __half22float2(*reinterpret_cast<__half2*>(&A0[ks][3]));
                t1 = fmaf(f.x, f.x, t1); t1 = fmaf(f.y, f.y, t1);
                f = __half22float2(*reinterpret_cast<__half2*>(&A1[ks][0]));
                t2 = fmaf(f.x, f.x, t2); t2 = fmaf(f.y, f.y, t2);
                f = __half22float2(*reinterpret_cast<__half2*>(&A1[ks][2]));
                t2 = fmaf(f.x, f.x, t2); t2 = fmaf(f.y, f.y, t2);
                f = __half22float2(*reinterpret_cast<__half2*>(&A1[ks][1]));
                t3 = fmaf(f.x, f.x, t3); t3 = fmaf(f.y, f.y, t3);
                f = __half22float2(*reinterpret_cast<__half2*>(&A1[ks][3]));
                t3 = fmaf(f.x, f.x, t3); t3 = fmaf(f.y, f.y, t3);
            }
            t0 += __shfl_xor_sync(~0u, t0, 1); t0 += __shfl_xor_sync(~0u, t0, 2);
            t1 += __shfl_xor_sync(~0u, t1, 1); t1 += __shfl_xor_sync(~0u, t1, 2);
            t2 += __shfl_xor_sync(~0u, t2, 1); t2 += __shfl_xor_sync(~0u, t2, 2);
            t3 += __shfl_xor_sync(~0u, t3, 1); t3 += __shfl_xor_sync(~0u, t3, 2);
            xq0 = t0; xq1 = t1; xq2 = t2; xq3 = t3;
        }

        // ---- scan: top-8 pair-key chains for rows +0, +8, +16, +24 ----
        uint32_t ka[8], kb[8], kc8[8], kd[8];
#pragma unroll
        for (int i = 0; i < 8; i++) { ka[i] = ~0u; kb[i] = ~0u; kc8[i] = ~0u; kd[i] = ~0u; }

        for (int ch2 = 0; ch2 < 4; ch2++) {
            const uint32_t bA = bA0 + ch2 * 16384, bB = bB0 + ch2 * 16384;
            const int chbase = (wh * 4 + ch2) * 128;
#pragma unroll 4
            for (int nt = 0; nt < 16; nt++) {
                uint32_t b0, b1, b2, b3, b4, b5, b6, b7;
                LDSM_X4(b0, b1, b2, b3, bA + nt * 1024);
                LDSM_X4(b4, b5, b6, b7, bB + nt * 1024);
                float c0 = 0.f, c1 = 0.f, c2 = 0.f, c3 = 0.f;
                float d0 = 0.f, d1 = 0.f, d2 = 0.f, d3 = 0.f;
                MMA16816(c0, c1, c2, c3, A0[0][0], A0[0][1], A0[0][2], A0[0][3], b0, b1);
                MMA16816(c0, c1, c2, c3, A0[1][0], A0[1][1], A0[1][2], A0[1][3], b2, b3);
                MMA16816(c0, c1, c2, c3, A0[2][0], A0[2][1], A0[2][2], A0[2][3], b4, b5);
                MMA16816(c0, c1, c2, c3, A0[3][0], A0[3][1], A0[3][2], A0[3][3], b6, b7);
                MMA16816(d0, d1, d2, d3, A1[0][0], A1[0][1], A1[0][2], A1[0][3], b0, b1);
                MMA16816(d0, d1, d2, d3, A1[1][0], A1[1][1], A1[1][2], A1[1][3], b2, b3);
                MMA16816(d0, d1, d2, d3, A1[2][0], A1[2][1], A1[2][2], A1[2][3], b4, b5);
                MMA16816(d0, d1, d2, d3, A1[3][0], A1[3][1], A1[3][2], A1[3][3], b6, b7);

                const int gc0 = chbase + nt * 8 + gcl;
                const uint32_t pidx = (uint32_t)(gc0 >> 1);
                float2 eq = *reinterpret_cast<const float2*>(s_esq + gc0);
                ins8(ka, (__float_as_uint(fminf(fmaf(-2.f, c0, xq0 + eq.x),
                                                fmaf(-2.f, c1, xq0 + eq.y))) & 0xFFFFFC00u) | pidx);
                ins8(kb, (__float_as_uint(fminf(fmaf(-2.f, c2, xq1 + eq.x),
                                                fmaf(-2.f, c3, xq1 + eq.y))) & 0xFFFFFC00u) | pidx);
                ins8(kc8, (__float_as_uint(fminf(fmaf(-2.f, d0, xq2 + eq.x),
                                                 fmaf(-2.f, d1, xq2 + eq.y))) & 0xFFFFFC00u) | pidx);
                ins8(kd, (__float_as_uint(fminf(fmaf(-2.f, d2, xq3 + eq.x),
                                                fmaf(-2.f, d3, xq3 + eq.y))) & 0xFFFFFC00u) | pidx);
            }
        }

        // merge top-8 lists across the 4 lanes of each row quad (snapshot first:
        // shuffle sources must not be mutated mid-merge)
#pragma unroll
        for (int m = 1; m <= 2; m <<= 1) {
            uint32_t sa[8], sb8[8], sc[8], sd[8];
#pragma unroll
            for (int i = 0; i < 8; i++) {
                sa[i] = __shfl_xor_sync(~0u, ka[i], m);
                sb8[i] = __shfl_xor_sync(~0u, kb[i], m);
                sc[i] = __shfl_xor_sync(~0u, kc8[i], m);
                sd[i] = __shfl_xor_sync(~0u, kd[i], m);
            }
#pragma unroll
            for (int i = 0; i < 8; i++) {
                ins8(ka, sa[i]);
                ins8(kb, sb8[i]);
                ins8(kc8, sc[i]);
                ins8(kd, sd[i]);
            }
        }

        // leaders publish per-half top-8 lists (+ xq from half 0)
        if ((lane & 3) == 0) {
            int r = rg * 32 + (lane >> 2);
            uint32_t* dst = s_keys + wh * 1024;
#pragma unroll
            for (int i = 0; i < 8; i++) {
                dst[r * 8 + i] = ka[i];
                dst[(r + 8) * 8 + i] = kb[i];
                dst[(r + 16) * 8 + i] = kc8[i];
                dst[(r + 24) * 8 + i] = kd[i];
            }
            if (wh == 0) {
                s_xsq[r] = xq0; s_xsq[r + 8] = xq1;
                s_xsq[r + 16] = xq2; s_xsq[r + 24] = xq3;
            }
        }
        __syncthreads();

        // finalize phase 1: two threads per row (even/odd codes of candidate pairs)
        {
            const int row = tid & 127;
            const int half = tid >> 7;
            uint32_t k[8];
#pragma unroll
            for (int i = 0; i < 8; i++) k[i] = s_keys[row * 8 + i];
#pragma unroll
            for (int i = 0; i < 8; i++) ins8(k, s_keys[1024 + row * 8 + i]);
            float m1 = __uint_as_float(k[0] & 0xFFFFFC00u);
            float m8 = __uint_as_float(k[7] & 0xFFFFFC00u);
            float margin = 0.0022f * sqrtf(s_xsq[row]) * emax + 0.06f;
            float bs = FLT_MAX;
            int bi = 0x7fffffff;
            if (m8 - m1 >= margin) {
                const float4* xrp =
                    reinterpret_cast<const float4*>(x + (size_t)(row0 + row) * VQ_D);
#pragma unroll
                for (int j = 0; j < 7; j++) {
                    float mj = __uint_as_float(k[j] & 0xFFFFFC00u);
                    if (j == 0 || mj - m1 < margin) {
                        int code = 2 * (int)(k[j] & 0x3FFu) + half;
                        float s = exact_score(xrp, e, code, s_esq[code]);
                        if (s < bs || (s == bs && code < bi)) { bs = s; bi = code; }
                    }
                }
            } else if (half == 0) {
                int slot = atomicAdd(&g_flag_count, 1);
                g_flag_rows[slot] = row0 + row;
            }
            s_dbs[tid] = bs;
            s_dbi[tid] = bi;
            if (half == 0) s_widx[row] = 2 * (int)(k[0] & 0x3FFu);  // placeholder
        }
        __syncthreads();

        // finalize phase 2: merge halves
        if (tid < ROWS) {
            float b0 = s_dbs[tid], b1 = s_dbs[tid + 128];
            int i0 = s_dbi[tid], i1 = s_dbi[tid + 128];
            if (i0 != 0x7fffffff || i1 != 0x7fffffff)
                s_widx[tid] = (b1 < b0 || (b1 == b0 && i1 < i0)) ? i1 : i0;
        }
        __syncthreads();

        // gather winning embeddings (fp32 codebook, L2-resident), coalesced writes
#pragma unroll
        for (int i = 0; i < 8; i++) {
            int idx4 = tid + i * THREADS;
            int r = idx4 >> 4, q = idx4 & 15;
            int id = s_widx[r];
            *reinterpret_cast<float4*>(out + (size_t)(row0 + r) * VQ_D + q * 4) =
                *reinterpret_cast<const float4*>(e + (size_t)id * VQ_D + q * 4);
        }
        __syncthreads();
    }
}

// ---------------- fallback: exact fp32 rescan of flagged rows (now very rare) ----------------
__global__ void __launch_bounds__(256) vq_fallback(const float* __restrict__ x,
                                                   const float* __restrict__ e,
                                                   float* __restrict__ out) {
    __shared__ float se[64][68];
    __shared__ float sq[64];
    const int tid = threadIdx.x;
    const int wid = tid >> 5, lid = tid & 31;
    const int cnt = g_flag_count;

    for (int base = blockIdx.x * 8; base < cnt; base += gridDim.x * 8) {
        const int rown = base + wid;
        const int row = (rown < cnt) ? g_flag_rows[rown] : -1;
        uint64_t xrp[32];
        if (row >= 0) {
            const float2* xp = reinterpret_cast<const float2*>(x + (size_t)row * VQ_D);
#pragma unroll
            for (int i = 0; i < 32; i++) xrp[i] = f2u64(xp[i]);
        }
        float bs = FLT_MAX;
        int bi = 0x7fffffff;
        for (int cb = 0; cb < VQ_K; cb += 64) {
            __syncthreads();
#pragma unroll
            for (int i = 0; i < 4; i++) {
                int idx4 = tid + i * 256;
                int r = idx4 >> 4, q = idx4 & 15;
                *reinterpret_cast<float4*>(&se[r][q * 4]) =
                    *reinterpret_cast<const float4*>(e + (size_t)(cb + r) * VQ_D + q * 4);
            }
            if (tid < 64) sq[tid] = g_esq[cb + tid];
            __syncthreads();
            if (row >= 0) {
#pragma unroll
                for (int j = 0; j < 2; j++) {
                    int c = j * 32 + lid;
                    const ulonglong2* ev = reinterpret_cast<const ulonglong2*>(&se[c][0]);
                    uint64_t a0 = 0, a1 = 0, a2 = 0, a3 = 0;
#pragma unroll
                    for (int i = 0; i < 8; i++) {
                        ulonglong2 ea = ev[2 * i], eb = ev[2 * i + 1];
                        FMA_F32X2(a0, xrp[4 * i + 0], ea.x);
                        FMA_F32X2(a1, xrp[4 * i + 1], ea.y);
                        FMA_F32X2(a2, xrp[4 * i + 2], eb.x);
                        FMA_F32X2(a3, xrp[4 * i + 3], eb.y);
                    }
                    uint64_t s01, s23, st;
                    ADD_F32X2(s01, a0, a1);
                    ADD_F32X2(s23, a2, a3);
                    ADD_F32X2(st, s01, s23);
                    float2 sv = u64f2(st);
                    float s = fmaf(-2.f, sv.x + sv.y, sq[c]);
                    int code = cb + c;
                    if (s < bs) { bs = s; bi = code; }
                }
            }
        }
        if (row >= 0) {
#pragma unroll
            for (int o = 16; o > 0; o >>= 1) {
                float os = __shfl_down_sync(0xFFFFFFFF, bs, o);
                int oi = __shfl_down_sync(0xFFFFFFFF, bi, o);
                if (os < bs || (os == bs && oi < bi)) { bs = os; bi = oi; }
            }
            bi = __shfl_sync(0xFFFFFFFF, bi, 0);
            if (lid < 16)
                *reinterpret_cast<float4*>(out + (size_t)row * VQ_D + lid * 4) =
                    *reinterpret_cast<const float4*>(e + (size_t)bi * VQ_D + lid * 4);
        }
    }
}

extern "C" void kernel_launch(void* const* d_in, const int* in_sizes, int n_in,
                              void* d_out, int out_size) {
    const float* x = (const float*)d_in[0];           // (131072, 64)
    const float* embeddings = (const float*)d_in[1];  // (1024, 64)
    float* out = (float*)d_out;

    cudaFuncSetAttribute(vq_main, cudaFuncAttributeMaxDynamicSharedMemorySize, SMEM_TOTAL);

    vq_prep_e<<<(VQ_K * 8) / 256, 256>>>(embeddings);
    vq_main<<<GRID_MAIN, THREADS, SMEM_TOTAL>>>(x, embeddings, out);
    vq_fallback<<<1024, 256>>>(x, embeddings, out);
}

// round 17
// speedup vs baseline: 1.1540x; 1.1540x over previous
#include <cuda_runtime.h>
#include <cuda_fp16.h>
#include <cstdint>
#include <cstring>
#include <cfloat>

// VectorQuantizer: B=131072, D=64, K=1024, fp32.
// R17 = R14 (persistent fp16 mma.sync, codebook in smem, direct A-fragment
// build from fp32 staging, pair-compressed keys) with TOP-5 pair keys:
// certification uses m5, duel covers pairs 1..4 within margin, so the exact
// fallback fires ~an order of magnitude less often. Only +4 registers vs R14.

#define VQ_B 131072
#define VQ_K 1024
#define VQ_D 64
#define ROWS 128
#define THREADS 256
#define NTILES (VQ_B / ROWS)   // 1024
#define GRID_MAIN 148
#define STG_PITCH 272
#define STG_BYTES (ROWS * STG_PITCH)  // 34816

__device__ float g_esq[VQ_K];
__device__ int g_emax2_bits = 0;
__device__ int g_flag_count;
__device__ int g_flag_rows[VQ_B];
__device__ __half g_eh[(size_t)VQ_K * VQ_D];   // fp16 e, granule-swizzled

// Dynamic smem layout (bytes)
#define ES_OFF     0         // 131072
#define STAGE_OFF  131072    // 2 * 34816 = 69632
#define ESQ_OFF    200704    // 4096
#define KEYS_OFF   204800    // [2][128][8] uint32 (5 used) = 8192
#define XSQ_OFF    212992    // 512
#define SMEM_TOTAL 213504

// ---------------- PTX helpers ----------------
static __device__ __forceinline__ uint32_t smem_u32(const void* p) {
    uint32_t a;
    asm("{ .reg .u64 t; cvta.to.shared.u64 t, %1; cvt.u32.u64 %0, t; }" : "=r"(a) : "l"(p));
    return a;
}
#define CP_ASYNC16(dst, src) \
    asm volatile("cp.async.cg.shared.global [%0], [%1], 16;" :: "r"(dst), "l"(src) : "memory")
#define CP_COMMIT() asm volatile("cp.async.commit_group;" ::: "memory")
#define CP_WAIT1() asm volatile("cp.async.wait_group 1;" ::: "memory")
#define LDSM_X4(r0, r1, r2, r3, a) \
    asm volatile("ldmatrix.sync.aligned.m8n8.x4.shared.b16 {%0,%1,%2,%3}, [%4];" \
                 : "=r"(r0), "=r"(r1), "=r"(r2), "=r"(r3) : "r"(a))
#define MMA16816(c0, c1, c2, c3, a0, a1, a2, a3, b0, b1) \
    asm volatile("mma.sync.aligned.m16n8k16.row.col.f32.f16.f16.f32 " \
                 "{%0,%1,%2,%3}, {%4,%5,%6,%7}, {%8,%9}, {%0,%1,%2,%3};" \
                 : "+f"(c0), "+f"(c1), "+f"(c2), "+f"(c3) \
                 : "r"(a0), "r"(a1), "r"(a2), "r"(a3), "r"(b0), "r"(b1))

// sorted top-5 insert (bubbling; k[0] <= ... <= k[4])
static __device__ __forceinline__ void ins5(uint32_t k[5], uint32_t u) {
#pragma unroll
    for (int i = 0; i < 5; i++) {
        uint32_t mx = max(k[i], u);
        k[i] = min(k[i], u);
        u = mx;
    }
}

// f32x2 packed math (fallback kernel)
#define FMA_F32X2(acc, a, b) asm("fma.rn.f32x2 %0, %1, %2, %0;" : "+l"(acc) : "l"(a), "l"(b))
#define ADD_F32X2(d, a, b) asm("add.rn.f32x2 %0, %1, %2;" : "=l"(d) : "l"(a), "l"(b))
static __device__ __forceinline__ float2 u64f2(uint64_t u) { float2 v; memcpy(&v, &u, 8); return v; }
static __device__ __forceinline__ uint64_t f2u64(float2 v) { uint64_t u; memcpy(&u, &v, 8); return u; }

static __device__ __forceinline__ uint32_t h2pack(float a, float b) {
    __half2 h = __floats2half2_rn(a, b);
    uint32_t u;
    memcpy(&u, &h, 4);
    return u;
}

// ---------------- prologue: e -> fp16 (granule-swizzled) + esq + emax ----------------
__global__ void vq_prep_e(const float* __restrict__ e) {
    int t = blockIdx.x * blockDim.x + threadIdx.x;
    if (t == 0) g_flag_count = 0;
    if (t >= VQ_K * 8) return;
    int c = t >> 3, g = t & 7;
    const float4* p = reinterpret_cast<const float4*>(e + (size_t)c * VQ_D + g * 8);
    float4 v0 = p[0], v1 = p[1];
    float s = v0.x * v0.x + v0.y * v0.y + v0.z * v0.z + v0.w * v0.w +
              v1.x * v1.x + v1.y * v1.y + v1.z * v1.z + v1.w * v1.w;
    __half2 h[4] = {__floats2half2_rn(v0.x, v0.y), __floats2half2_rn(v0.z, v0.w),
                    __floats2half2_rn(v1.x, v1.y), __floats2half2_rn(v1.z, v1.w)};
    uint4 pk;
    memcpy(&pk, h, 16);
    int gp = g ^ (c & 7);
    *reinterpret_cast<uint4*>(&g_eh[(size_t)c * VQ_D + gp * 8]) = pk;
    s += __shfl_down_sync(~0u, s, 4, 8);
    s += __shfl_down_sync(~0u, s, 2, 8);
    s += __shfl_down_sync(~0u, s, 1, 8);
    if (g == 0) {
        g_esq[c] = s;
        atomicMax(&g_emax2_bits, __float_as_int(s));
    }
}

// exact fp32 score with 4 split accumulators
static __device__ __forceinline__ float exact_score(const float4* xr, const float* e, int code,
                                                    float esq) {
    const float4* er = reinterpret_cast<const float4*>(e + (size_t)code * VQ_D);
    float a0 = 0.f, a1 = 0.f, a2 = 0.f, a3 = 0.f;
#pragma unroll
    for (int i = 0; i < 16; i += 4) {
        float4 xa = xr[i], ba = er[i];
        float4 xb = xr[i + 1], bb = er[i + 1];
        float4 xc = xr[i + 2], bc = er[i + 2];
        float4 xd = xr[i + 3], bd = er[i + 3];
        a0 = fmaf(xa.x, ba.x, a0); a0 = fmaf(xa.y, ba.y, a0);
        a0 = fmaf(xa.z, ba.z, a0); a0 = fmaf(xa.w, ba.w, a0);
        a1 = fmaf(xb.x, bb.x, a1); a1 = fmaf(xb.y, bb.y, a1);
        a1 = fmaf(xb.z, bb.z, a1); a1 = fmaf(xb.w, bb.w, a1);
        a2 = fmaf(xc.x, bc.x, a2); a2 = fmaf(xc.y, bc.y, a2);
        a2 = fmaf(xc.z, bc.z, a2); a2 = fmaf(xc.w, bc.w, a2);
        a3 = fmaf(xd.x, bd.x, a3); a3 = fmaf(xd.y, bd.y, a3);
        a3 = fmaf(xd.z, bd.z, a3); a3 = fmaf(xd.w, bd.w, a3);
    }
    return fmaf(-2.f, (a0 + a1) + (a2 + a3), esq);
}

// ---------------- main ----------------
__global__ void __launch_bounds__(THREADS, 1) vq_main(const float* __restrict__ x,
                                                      const float* __restrict__ e,
                                                      float* __restrict__ out) {
    extern __shared__ __align__(16) unsigned char dsm[];
    const uint32_t sb = smem_u32(dsm);
    float* s_esq = reinterpret_cast<float*>(dsm + ESQ_OFF);
    uint32_t* s_keys = reinterpret_cast<uint32_t*>(dsm + KEYS_OFF);  // [2][128][8]
    float* s_xsq = reinterpret_cast<float*>(dsm + XSQ_OFF);
    __shared__ int s_widx[ROWS];

    const int tid = threadIdx.x;
    const int warp = tid >> 5, lane = tid & 31;
    const int rg = warp & 3;
    const int wh = warp >> 2;

    auto stage_tile = [&](int tile, int b) {
#pragma unroll
        for (int i = 0; i < 8; i++) {
            int idx = tid + i * THREADS;
            int r = idx >> 4, q = idx & 15;
            CP_ASYNC16(sb + STAGE_OFF + b * STG_BYTES + r * STG_PITCH + q * 16,
                       reinterpret_cast<const char*>(x) +
                           ((size_t)tile * ROWS + r) * (VQ_D * 4) + q * 16);
        }
    };

#pragma unroll
    for (int i = 0; i < 32; i++) {
        int line = tid + i * THREADS;
        CP_ASYNC16(sb + ES_OFF + line * 16, reinterpret_cast<const char*>(g_eh) + line * 16);
    }
    CP_ASYNC16(sb + ESQ_OFF + tid * 16, reinterpret_cast<const char*>(g_esq) + tid * 16);
    stage_tile(blockIdx.x, 0);
    CP_COMMIT();
    if (blockIdx.x + GRID_MAIN < NTILES) stage_tile(blockIdx.x + GRID_MAIN, 1);
    CP_COMMIT();

    const float emax = sqrtf(__int_as_float(g_emax2_bits));
    const int lc = lane & 7, lm = lane >> 3;
    const uint32_t bA0 = sb + ES_OFF + (wh * 4) * 16384 + (lc * 64 + ((lm ^ lc) * 8)) * 2;
    const uint32_t bB0 = sb + ES_OFF + (wh * 4) * 16384 + (lc * 64 + (((lm + 4) ^ lc) * 8)) * 2;
    const int gcl = 2 * (lane & 3);

    int buf = 0;
    for (int tile = blockIdx.x; tile < NTILES; tile += GRID_MAIN, buf ^= 1) {
        const int row0 = tile * ROWS;

        CP_WAIT1();
        __syncthreads();

        // A fragments directly from fp32 staging (canonical m16n8k16 layout)
        uint32_t A0[4][4], A1[4][4];
        {
            const unsigned char* stg = dsm + STAGE_OFF + buf * STG_BYTES;
            const int qr = lane >> 2;
            const int kcn = (lane & 3) * 2;
            const int ra = rg * 32 + qr;
#pragma unroll
            for (int ks = 0; ks < 4; ks++) {
                const int k0 = 16 * ks + kcn;
#pragma unroll
                for (int half = 0; half < 2; half++) {
                    uint32_t (*A)[4] = half ? A1 : A0;
                    const int r_lo = ra + half * 16;
                    const int r_hi = r_lo + 8;
                    float2 v0 = *reinterpret_cast<const float2*>(stg + r_lo * STG_PITCH + k0 * 4);
                    float2 v1 = *reinterpret_cast<const float2*>(stg + r_hi * STG_PITCH + k0 * 4);
                    float2 v2 = *reinterpret_cast<const float2*>(stg + r_lo * STG_PITCH + (k0 + 8) * 4);
                    float2 v3 = *reinterpret_cast<const float2*>(stg + r_hi * STG_PITCH + (k0 + 8) * 4);
                    A[ks][0] = h2pack(v0.x, v0.y);
                    A[ks][1] = h2pack(v1.x, v1.y);
                    A[ks][2] = h2pack(v2.x, v2.y);
                    A[ks][3] = h2pack(v3.x, v3.y);
                }
            }
        }
        __syncthreads();

        if (tile + 2 * GRID_MAIN < NTILES) stage_tile(tile + 2 * GRID_MAIN, buf);
        CP_COMMIT();

        // per-row squared norms from A fragments
        float xq0, xq1, xq2, xq3;
        {
            float t0 = 0.f, t1 = 0.f, t2 = 0.f, t3 = 0.f;
#pragma unroll
            for (int ks = 0; ks < 4; ks++) {
                float2 f;
                f = __half22float2(*reinterpret_cast<__half2*>(&A0[ks][0]));
                t0 = fmaf(f.x, f.x, t0); t0 = fmaf(f.y, f.y, t0);
                f = __half22float2(*reinterpret_cast<__half2*>(&A0[ks][2]));
                t0 = fmaf(f.x, f.x, t0); t0 = fmaf(f.y, f.y, t0);
                f = __half22float2(*reinterpret_cast<__half2*>(&A0[ks][1]));
                t1 = fmaf(f.x, f.x, t1); t1 = fmaf(f.y, f.y, t1);
                f = __half22float2(*reinterpret_cast<__half2*>(&A0[ks][3]));
                t1 = fmaf(f.x, f.x, t1); t1 = fmaf(f.y, f.y, t1);
                f = __half22float2(*reinterpret_cast<__half2*>(&A1[ks][0]));
                t2 = fmaf(f.x, f.x, t2); t2 = fmaf(f.y, f.y, t2);
                f = __half22float2(*reinterpret_cast<__half2*>(&A1[ks][2]));
                t2 = fmaf(f.x, f.x, t2); t2 = fmaf(f.y, f.y, t2);
                f = __half22float2(*reinterpret_cast<__half2*>(&A1[ks][1]));
                t3 = fmaf(f.x, f.x, t3); t3 = fmaf(f.y, f.y, t3);
                f = __half22float2(*reinterpret_cast<__half2*>(&A1[ks][3]));
                t3 = fmaf(f.x, f.x, t3); t3 = fmaf(f.y, f.y, t3);
            }
            t0 += __shfl_xor_sync(~0u, t0, 1); t0 += __shfl_xor_sync(~0u, t0, 2);
            t1 += __shfl_xor_sync(~0u, t1, 1); t1 += __shfl_xor_sync(~0u, t1, 2);
            t2 += __shfl_xor_sync(~0u, t2, 1); t2 += __shfl_xor_sync(~0u, t2, 2);
            t3 += __shfl_xor_sync(~0u, t3, 1); t3 += __shfl_xor_sync(~0u, t3, 2);
            xq0 = t0; xq1 = t1; xq2 = t2; xq3 = t3;
        }

        // ---- scan: top-5 pair-key chains for rows +0, +8, +16, +24 ----
        uint32_t ka[5], kb[5], kc[5], kd[5];
#pragma unroll
        for (int i = 0; i < 5; i++) { ka[i] = ~0u; kb[i] = ~0u; kc[i] = ~0u; kd[i] = ~0u; }

        for (int ch2 = 0; ch2 < 4; ch2++) {
            const uint32_t bA = bA0 + ch2 * 16384, bB = bB0 + ch2 * 16384;
            const int chbase = (wh * 4 + ch2) * 128;
#pragma unroll 4
            for (int nt = 0; nt < 16; nt++) {
                uint32_t b0, b1, b2, b3, b4, b5, b6, b7;
                LDSM_X4(b0, b1, b2, b3, bA + nt * 1024);
                LDSM_X4(b4, b5, b6, b7, bB + nt * 1024);
                float c0 = 0.f, c1 = 0.f, c2 = 0.f, c3 = 0.f;
                float d0 = 0.f, d1 = 0.f, d2 = 0.f, d3 = 0.f;
                MMA16816(c0, c1, c2, c3, A0[0][0], A0[0][1], A0[0][2], A0[0][3], b0, b1);
                MMA16816(c0, c1, c2, c3, A0[1][0], A0[1][1], A0[1][2], A0[1][3], b2, b3);
                MMA16816(c0, c1, c2, c3, A0[2][0], A0[2][1], A0[2][2], A0[2][3], b4, b5);
                MMA16816(c0, c1, c2, c3, A0[3][0], A0[3][1], A0[3][2], A0[3][3], b6, b7);
                MMA16816(d0, d1, d2, d3, A1[0][0], A1[0][1], A1[0][2], A1[0][3], b0, b1);
                MMA16816(d0, d1, d2, d3, A1[1][0], A1[1][1], A1[1][2], A1[1][3], b2, b3);
                MMA16816(d0, d1, d2, d3, A1[2][0], A1[2][1], A1[2][2], A1[2][3], b4, b5);
                MMA16816(d0, d1, d2, d3, A1[3][0], A1[3][1], A1[3][2], A1[3][3], b6, b7);

                const int gc0 = chbase + nt * 8 + gcl;
                const uint32_t pidx = (uint32_t)(gc0 >> 1);
                float2 eq = *reinterpret_cast<const float2*>(s_esq + gc0);
                ins5(ka, (__float_as_uint(fminf(fmaf(-2.f, c0, xq0 + eq.x),
                                                fmaf(-2.f, c1, xq0 + eq.y))) & 0xFFFFFC00u) | pidx);
                ins5(kb, (__float_as_uint(fminf(fmaf(-2.f, c2, xq1 + eq.x),
                                                fmaf(-2.f, c3, xq1 + eq.y))) & 0xFFFFFC00u) | pidx);
                ins5(kc, (__float_as_uint(fminf(fmaf(-2.f, d0, xq2 + eq.x),
                                                fmaf(-2.f, d1, xq2 + eq.y))) & 0xFFFFFC00u) | pidx);
                ins5(kd, (__float_as_uint(fminf(fmaf(-2.f, d2, xq3 + eq.x),
                                                fmaf(-2.f, d3, xq3 + eq.y))) & 0xFFFFFC00u) | pidx);
            }
        }

        // merge top-5 lists across the 4 lanes of each row quad (snapshot first)
#pragma unroll
        for (int m = 1; m <= 2; m <<= 1) {
            uint32_t sa[5], sb5[5], sc[5], sd[5];
#pragma unroll
            for (int i = 0; i < 5; i++) {
                sa[i] = __shfl_xor_sync(~0u, ka[i], m);
                sb5[i] = __shfl_xor_sync(~0u, kb[i], m);
                sc[i] = __shfl_xor_sync(~0u, kc[i], m);
                sd[i] = __shfl_xor_sync(~0u, kd[i], m);
            }
#pragma unroll
            for (int i = 0; i < 5; i++) {
                ins5(ka, sa[i]);
                ins5(kb, sb5[i]);
                ins5(kc, sc[i]);
                ins5(kd, sd[i]);
            }
        }

        // leaders publish per-half top-5 lists (+ xq from half 0)
        if ((lane & 3) == 0) {
            int r = rg * 32 + (lane >> 2);
            uint32_t* dst = s_keys + wh * 1024;
#pragma unroll
            for (int i = 0; i < 5; i++) {
                dst[r * 8 + i] = ka[i];
                dst[(r + 8) * 8 + i] = kb[i];
                dst[(r + 16) * 8 + i] = kc[i];
                dst[(r + 24) * 8 + i] = kd[i];
            }
            if (wh == 0) {
                s_xsq[r] = xq0; s_xsq[r + 8] = xq1;
                s_xsq[r + 16] = xq2; s_xsq[r + 24] = xq3;
            }
        }
        __syncthreads();

        // finalize: one thread per row — merge halves, certify with m5,
        // duel within-margin pairs (<=4 pairs, 8 codes), or flag (rare)
        if (tid < ROWS) {
            uint32_t k[5];
#pragma unroll
            for (int i = 0; i < 5; i++) k[i] = s_keys[tid * 8 + i];
#pragma unroll
            for (int i = 0; i < 5; i++) ins5(k, s_keys[1024 + tid * 8 + i]);
            float m1 = __uint_as_float(k[0] & 0xFFFFFC00u);
            float m2 = __uint_as_float(k[1] & 0xFFFFFC00u);
            float m5 = __uint_as_float(k[4] & 0xFFFFFC00u);
            float margin = 0.0022f * sqrtf(s_xsq[tid]) * emax + 0.06f;
            int np;
            if (m2 - m1 >= margin) np = 1;
            else if (m5 - m1 >= margin) np = 4;
            else np = 0;
            int winner = 2 * (int)(k[0] & 0x3FFu);  // placeholder if flagged
            if (np > 0) {
                const float4* xr = reinterpret_cast<const float4*>(x + (size_t)(row0 + tid) * VQ_D);
                float bs = FLT_MAX;
                int bi = 0x7fffffff;
#pragma unroll
                for (int j = 0; j < 4; j++) {
                    if (j >= np) break;
                    float mj = __uint_as_float(k[j] & 0xFFFFFC00u);
                    if (j == 0 || mj - m1 < margin) {
                        int c0 = 2 * (int)(k[j] & 0x3FFu);
#pragma unroll
                        for (int tt = 0; tt < 2; tt++) {
                            int code = c0 + tt;
                            float s = exact_score(xr, e, code, s_esq[code]);
                            if (s < bs || (s == bs && code < bi)) { bs = s; bi = code; }
                        }
                    }
                }
                winner = bi;
            } else {
                int slot = atomicAdd(&g_flag_count, 1);
                g_flag_rows[slot] = row0 + tid;
            }
            s_widx[tid] = winner;
        }
        __syncthreads();

        // gather winning embeddings (fp32 codebook, L2-resident), coalesced writes
#pragma unroll
        for (int i = 0; i < 8; i++) {
            int idx4 = tid + i * THREADS;
            int r = idx4 >> 4, q = idx4 & 15;
            int id = s_widx[r];
            *reinterpret_cast<float4*>(out + (size_t)(row0 + r) * VQ_D + q * 4) =
                *reinterpret_cast<const float4*>(e + (size_t)id * VQ_D + q * 4);
        }
        __syncthreads();
    }
}

// ---------------- fallback: exact fp32 rescan of flagged rows (rare) ----------------
__global__ void __launch_bounds__(256) vq_fallback(const float* __restrict__ x,
                                                   const float* __restrict__ e,
                                                   float* __restrict__ out) {
    __shared__ float se[64][68];
    __shared__ float sq[64];
    const int tid = threadIdx.x;
    const int wid = tid >> 5, lid = tid & 31;
    const int cnt = g_flag_count;

    for (int base = blockIdx.x * 8; base < cnt; base += gridDim.x * 8) {
        const int rown = base + wid;
        const int row = (rown < cnt) ? g_flag_rows[rown] : -1;
        uint64_t xrp[32];
        if (row >= 0) {
            const float2* xp = reinterpret_cast<const float2*>(x + (size_t)row * VQ_D);
#pragma unroll
            for (int i = 0; i < 32; i++) xrp[i] = f2u64(xp[i]);
        }
        float bs = FLT_MAX;
        int bi = 0x7fffffff;
        for (int cb = 0; cb < VQ_K; cb += 64) {
            __syncthreads();
#pragma unroll
            for (int i = 0; i < 4; i++) {
                int idx4 = tid + i * 256;
                int r = idx4 >> 4, q = idx4 & 15;
                *reinterpret_cast<float4*>(&se[r][q * 4]) =
                    *reinterpret_cast<const float4*>(e + (size_t)(cb + r) * VQ_D + q * 4);
            }
            if (tid < 64) sq[tid] = g_esq[cb + tid];
            __syncthreads();
            if (row >= 0) {
#pragma unroll
                for (int j = 0; j < 2; j++) {
                    int c = j * 32 + lid;
                    const ulonglong2* ev = reinterpret_cast<const ulonglong2*>(&se[c][0]);
                    uint64_t a0 = 0, a1 = 0, a2 = 0, a3 = 0;
#pragma unroll
                    for (int i = 0; i < 8; i++) {
                        ulonglong2 ea = ev[2 * i], eb = ev[2 * i + 1];
                        FMA_F32X2(a0, xrp[4 * i + 0], ea.x);
                        FMA_F32X2(a1, xrp[4 * i + 1], ea.y);
                        FMA_F32X2(a2, xrp[4 * i + 2], eb.x);
                        FMA_F32X2(a3, xrp[4 * i + 3], eb.y);
                    }
                    uint64_t s01, s23, st;
                    ADD_F32X2(s01, a0, a1);
                    ADD_F32X2(s23, a2, a3);
                    ADD_F32X2(st, s01, s23);
                    float2 sv = u64f2(st);
                    float s = fmaf(-2.f, sv.x + sv.y, sq[c]);
                    int code = cb + c;
                    if (s < bs) { bs = s; bi = code; }
                }
            }
        }
        if (row >= 0) {
#pragma unroll
            for (int o = 16; o > 0; o >>= 1) {
                float os = __shfl_down_sync(0xFFFFFFFF, bs, o);
                int oi = __shfl_down_sync(0xFFFFFFFF, bi, o);
                if (os < bs || (os == bs && oi < bi)) { bs = os; bi = oi; }
            }
            bi = __shfl_sync(0xFFFFFFFF, bi, 0);
            if (lid < 16)
                *reinterpret_cast<float4*>(out + (size_t)row * VQ_D + lid * 4) =
                    *reinterpret_cast<const float4*>(e + (size_t)bi * VQ_D + lid * 4);
        }
    }
}

extern "C" void kernel_launch(void* const* d_in, const int* in_sizes, int n_in,
                              void* d_out, int out_size) {
    const float* x = (const float*)d_in[0];           // (131072, 64)
    const float* embeddings = (const float*)d_in[1];  // (1024, 64)
    float* out = (float*)d_out;

    cudaFuncSetAttribute(vq_main, cudaFuncAttributeMaxDynamicSharedMemorySize, SMEM_TOTAL);

    vq_prep_e<<<(VQ_K * 8) / 256, 256>>>(embeddings);
    vq_main<<<GRID_MAIN, THREADS, SMEM_TOTAL>>>(x, embeddings, out);
    vq_fallback<<<1024, 256>>>(x, embeddings, out);
}